// round 1
// baseline (speedup 1.0000x reference)
#include <cuda_runtime.h>
#include <math.h>

#define B_ 4
#define T_ 12
#define N_ 768
#define F_ 32
#define H_ 64
#define E_ 24576
#define M_ (B_*T_*N_)
#define EPS_ 1e-5f

// ---------------- device scratch (module-load allocated, allowed) ----------------
__device__ float g_h [M_*H_];
__device__ float g_z1[M_*H_];
__device__ float g_z2[M_*H_];
__device__ float g_z3[M_*H_];
__device__ float g_wT[4*3*3*H_*H_];      // [ls][kt][g][hi][ho]
__device__ float g_deg[N_];
__device__ int   g_cnt[N_];
__device__ int   g_rowptr[N_+1];
__device__ int   g_cursor[N_];
__device__ float g_dinv[N_];
__device__ int   g_ccol[E_];
__device__ float g_cw[E_];
__device__ float g_mu[N_];
__device__ float g_rstdv[N_];
__device__ float g_av[B_*N_*32];
__device__ float g_cv[B_*N_*32];

// ---------------- graph preprocessing ----------------
__global__ void k_prep0() {
    int i = blockIdx.x*256 + threadIdx.x;
    if (i < N_) { g_deg[i] = 0.f; g_cnt[i] = 0; }
}

__global__ void k_prep1(const int* __restrict__ ei, const float* __restrict__ ew) {
    int e = blockIdx.x*256 + threadIdx.x;
    if (e < E_) {
        int r = ei[e];
        atomicAdd(&g_deg[r], ew[e]);
        atomicAdd(&g_cnt[r], 1);
    }
}

__global__ void k_scan() {   // single block, 1024 threads
    __shared__ int s[1024];
    int tid = threadIdx.x;
    s[tid] = (tid < N_) ? g_cnt[tid] : 0;
    if (tid < N_) {
        float d = g_deg[tid];
        g_dinv[tid] = (d > 0.f) ? rsqrtf(fmaxf(d, 1e-12f)) : 0.f;
    }
    __syncthreads();
    for (int off = 1; off < 1024; off <<= 1) {
        int v = (tid >= off) ? s[tid-off] : 0;
        __syncthreads();
        s[tid] += v;
        __syncthreads();
    }
    if (tid < N_) {
        int ex = (tid == 0) ? 0 : s[tid-1];
        g_rowptr[tid] = ex;
        g_cursor[tid] = ex;
    }
    if (tid == N_-1) g_rowptr[N_] = s[N_-1];
}

__global__ void k_scatter(const int* __restrict__ ei, const float* __restrict__ ew) {
    int e = blockIdx.x*256 + threadIdx.x;
    if (e < E_) {
        int r = ei[e], c = ei[E_+e];
        int pos = atomicAdd(&g_cursor[r], 1);
        g_ccol[pos] = c;
        g_cw[pos] = -g_dinv[r] * ew[e] * g_dinv[c];
    }
}

// transpose tc_w (L,2,3,ho,hi,kt) -> g_wT [ls][kt][g][hi][ho]
__global__ void k_wt(const float* __restrict__ w) {
    int idx = blockIdx.x*256 + threadIdx.x;   // 0..147455
    int ho = idx & 63;
    int hi = (idx >> 6) & 63;
    int g  = (idx >> 12) % 3;
    int kt = (idx / 12288) % 3;
    int ls = idx / 36864;
    g_wT[idx] = w[(((ls*3 + g)*64 + ho)*64 + hi)*3 + kt];
}

// ---------------- input projection ----------------
__global__ void __launch_bounds__(256) k_inproj(const float* __restrict__ x,
    const float* __restrict__ pw, const float* __restrict__ pb) {
    __shared__ float xs[4][32];
    int rl = threadIdx.x >> 6, j = threadIdx.x & 63;
    int row = blockIdx.x*4 + rl;
    if (j < 32) xs[rl][j] = x[(long)row*F_ + j];
    __syncthreads();
    float acc = pb[j];
#pragma unroll
    for (int f = 0; f < 32; f++) acc += xs[rl][f] * pw[f*64 + j];
    g_h[(long)row*H_ + j] = acc;
}

// ---------------- gated temporal conv (3 shifted GEMMs, fused gates) ----------------
__global__ void __launch_bounds__(256) k_tconv(
    const float* __restrict__ in, float* __restrict__ out,
    const float* __restrict__ wT, const float* __restrict__ bias) {
    __shared__ float As[64][64];
    __shared__ float Ws[3][32][64];
    const int tid  = threadIdx.x;
    const int r0   = blockIdx.x * 64;
    const int t    = (r0 / N_) % T_;
    const int col4 = (tid & 15) * 4;
    const int row4 = (tid >> 4) * 4;
    const int lrow = tid >> 4;
    const int lhi  = (tid & 15) * 4;

    float acc[3][4][4];
#pragma unroll
    for (int g = 0; g < 3; g++)
#pragma unroll
        for (int i = 0; i < 4; i++)
#pragma unroll
            for (int j = 0; j < 4; j++) acc[g][i][j] = 0.f;

    for (int kt = 0; kt < 3; kt++) {
        const int dt = kt - 1;
        const bool valid = ((unsigned)(t + dt)) < (unsigned)T_;
        __syncthreads();
        const float* src = in + (long)(r0 + dt*N_) * H_;
#pragma unroll
        for (int rr = 0; rr < 4; rr++) {
            int row = lrow + rr*16;
            float4 v = make_float4(0.f, 0.f, 0.f, 0.f);
            if (valid) v = *(const float4*)(src + row*H_ + lhi);
            *(float4*)(&As[row][lhi]) = v;
        }
        for (int hic = 0; hic < 64; hic += 32) {
            __syncthreads();
#pragma unroll
            for (int q = 0; q < 6; q++) {
                int idx = q*256 + tid;       // 0..1535 float4 units
                int ho4 = (idx & 15) * 4;
                int hig = idx >> 4;          // 0..95
                int g  = hig >> 5;
                int hr = hig & 31;
                *(float4*)(&Ws[g][hr][ho4]) =
                    *(const float4*)(wT + ((kt*3 + g)*64 + hic + hr)*64 + ho4);
            }
            __syncthreads();
#pragma unroll 8
            for (int hh = 0; hh < 32; hh++) {
                float av[4];
#pragma unroll
                for (int i = 0; i < 4; i++) av[i] = As[row4+i][hic+hh];
#pragma unroll
                for (int g = 0; g < 3; g++) {
                    float4 w = *(float4*)(&Ws[g][hh][col4]);
                    float wa[4] = {w.x, w.y, w.z, w.w};
#pragma unroll
                    for (int i = 0; i < 4; i++)
#pragma unroll
                        for (int j = 0; j < 4; j++)
                            acc[g][i][j] += av[i] * wa[j];
                }
            }
        }
    }
    // epilogue: relu(g0 * sigmoid(g1) + g2), biases per gate
#pragma unroll
    for (int i = 0; i < 4; i++) {
        float r[4];
#pragma unroll
        for (int j = 0; j < 4; j++) {
            int ho = col4 + j;
            float y0 = acc[0][i][j] + bias[ho];
            float y1 = acc[1][i][j] + bias[64 + ho];
            float y2 = acc[2][i][j] + bias[128 + ho];
            float s = 1.f / (1.f + __expf(-y1));
            r[j] = fmaxf(y0*s + y2, 0.f);
        }
        float4 o = make_float4(r[0], r[1], r[2], r[3]);
        *(float4*)(out + (long)(r0 + row4 + i)*H_ + col4) = o;
    }
}

// ---------------- Laplacian propagation (CSR gather) ----------------
__global__ void __launch_bounds__(256) k_lhat(const float* __restrict__ z, float* __restrict__ out) {
    const int n   = blockIdx.x;
    const int tid = threadIdx.x;
    const int h   = tid & 63;
    const int btg = tid >> 6;     // 0..3, each handles 12 (b,t) slices
    __shared__ int   s_col[256];
    __shared__ float s_w[256];
    const int e0 = g_rowptr[n], e1 = g_rowptr[n+1];
    float acc[12];
#pragma unroll
    for (int q = 0; q < 12; q++) acc[q] = 0.f;
    for (int base = e0; base < e1; base += 256) {
        int cnt = min(256, e1 - base);
        __syncthreads();
        if (tid < cnt) { s_col[tid] = g_ccol[base + tid]; s_w[tid] = g_cw[base + tid]; }
        __syncthreads();
        for (int e = 0; e < cnt; e++) {
            const float* zp = z + ((long)(btg*12)*N_ + s_col[e])*H_ + h;
            float w = s_w[e];
#pragma unroll
            for (int q = 0; q < 12; q++) acc[q] += w * zp[(long)q * N_ * H_];
        }
    }
#pragma unroll
    for (int q = 0; q < 12; q++)
        out[((long)(btg*12 + q)*N_ + n)*H_ + h] = acc[q];
}

// ---------------- cheb combine: relu(z0@th0 + z1@th1 + b) ----------------
__global__ void __launch_bounds__(256) k_cheb(
    const float* __restrict__ z0, const float* __restrict__ z1,
    float* __restrict__ out,
    const float* __restrict__ th, const float* __restrict__ cb) {
    __shared__ float As[2][64][64];
    __shared__ float Ws[2][16][64];
    const int tid  = threadIdx.x;
    const int r0   = blockIdx.x * 64;
    const int col4 = (tid & 15) * 4;
    const int row4 = (tid >> 4) * 4;
    const int lrow = tid >> 4;
    const int lhi  = (tid & 15) * 4;

    float acc[4][4];
#pragma unroll
    for (int i = 0; i < 4; i++)
#pragma unroll
        for (int j = 0; j < 4; j++) acc[i][j] = 0.f;

#pragma unroll
    for (int rr = 0; rr < 4; rr++) {
        int row = lrow + rr*16;
        *(float4*)(&As[0][row][lhi]) = *(const float4*)(z0 + (long)(r0 + row)*H_ + lhi);
        *(float4*)(&As[1][row][lhi]) = *(const float4*)(z1 + (long)(r0 + row)*H_ + lhi);
    }
    for (int hic = 0; hic < 64; hic += 16) {
        __syncthreads();
#pragma unroll
        for (int q = 0; q < 2; q++) {
            int idx = q*256 + tid;      // 0..511 float4 units
            int ho4 = (idx & 15) * 4;
            int rr  = idx >> 4;         // 0..31
            int k   = rr >> 4, hr = rr & 15;
            *(float4*)(&Ws[k][hr][ho4]) =
                *(const float4*)(th + (k*64 + hic + hr)*64 + ho4);
        }
        __syncthreads();
#pragma unroll
        for (int hh = 0; hh < 16; hh++) {
            float av[4], bv[4];
#pragma unroll
            for (int i = 0; i < 4; i++) {
                av[i] = As[0][row4+i][hic+hh];
                bv[i] = As[1][row4+i][hic+hh];
            }
            float4 w0 = *(float4*)(&Ws[0][hh][col4]);
            float4 w1 = *(float4*)(&Ws[1][hh][col4]);
            float w0a[4] = {w0.x, w0.y, w0.z, w0.w};
            float w1a[4] = {w1.x, w1.y, w1.z, w1.w};
#pragma unroll
            for (int i = 0; i < 4; i++)
#pragma unroll
                for (int j = 0; j < 4; j++) {
                    acc[i][j] += av[i] * w0a[j];
                    acc[i][j] += bv[i] * w1a[j];
                }
        }
    }
#pragma unroll
    for (int i = 0; i < 4; i++) {
        float4 o;
        o.x = fmaxf(acc[i][0] + cb[col4+0], 0.f);
        o.y = fmaxf(acc[i][1] + cb[col4+1], 0.f);
        o.z = fmaxf(acc[i][2] + cb[col4+2], 0.f);
        o.w = fmaxf(acc[i][3] + cb[col4+3], 0.f);
        *(float4*)(out + (long)(r0 + row4 + i)*H_ + col4) = o;
    }
}

// ---------------- BatchNorm stats per node (double accumulation) ----------------
__global__ void __launch_bounds__(256) k_bnstats(const float* __restrict__ z) {
    const int n = blockIdx.x;
    const int tid = threadIdx.x;
    double s = 0.0, ss = 0.0;
    for (int idx = tid; idx < B_*T_*H_; idx += 256) {
        int bt = idx >> 6, h = idx & 63;
        float v = z[((long)bt*N_ + n)*H_ + h];
        s += v; ss += (double)v * v;
    }
    __shared__ double sh_s[8], sh_ss[8];
#pragma unroll
    for (int off = 16; off; off >>= 1) {
        s  += __shfl_xor_sync(0xffffffffu, s, off);
        ss += __shfl_xor_sync(0xffffffffu, ss, off);
    }
    int w = tid >> 5, l = tid & 31;
    if (l == 0) { sh_s[w] = s; sh_ss[w] = ss; }
    __syncthreads();
    if (tid == 0) {
        double ts = 0.0, tss = 0.0;
        for (int q = 0; q < 8; q++) { ts += sh_s[q]; tss += sh_ss[q]; }
        double mu  = ts / (double)(B_*T_*H_);
        double var = tss / (double)(B_*T_*H_) - mu*mu;
        g_mu[n]    = (float)mu;
        g_rstdv[n] = rsqrtf((float)var + EPS_);
    }
}

// ---------------- BN apply + LayerNorm + residual into g_h ----------------
__global__ void __launch_bounds__(256) k_bnln(
    const float* __restrict__ z,
    const float* __restrict__ bng, const float* __restrict__ bnb,
    const float* __restrict__ lng, const float* __restrict__ lnb) {
    int warp = threadIdx.x >> 5, lane = threadIdx.x & 31;
    int row = blockIdx.x*8 + warp;
    int n = row % N_;
    float mu = g_mu[n], rs = g_rstdv[n];
    float bg = bng[n] * rs, bb = bnb[n];
    float v0 = z[(long)row*H_ + lane];
    float v1 = z[(long)row*H_ + lane + 32];
    float u0 = (v0 - mu)*bg + bb;
    float u1 = (v1 - mu)*bg + bb;
    float sm = u0 + u1;
#pragma unroll
    for (int off = 16; off; off >>= 1) sm += __shfl_xor_sync(0xffffffffu, sm, off);
    float m = sm * (1.f/64.f);
    float d0 = u0 - m, d1 = u1 - m;
    float q = d0*d0 + d1*d1;
#pragma unroll
    for (int off = 16; off; off >>= 1) q += __shfl_xor_sync(0xffffffffu, q, off);
    float r = rsqrtf(q*(1.f/64.f) + EPS_);
    float* hp = g_h + (long)row*H_;
    hp[lane]      += d0*r*lng[lane]      + lnb[lane];
    hp[lane + 32] += d1*r*lng[lane + 32] + lnb[lane + 32];
}

// ---------------- head: a = emb@W1[:64], c = emb@W1[64:] + b1 ----------------
__global__ void __launch_bounds__(256) k_emb(const float* __restrict__ w1, const float* __restrict__ b1) {
    __shared__ float es[4][64];
    int rl = threadIdx.x >> 6, j = threadIdx.x & 63;
    int row = blockIdx.x*4 + rl;          // 0..3071
    int b = row / N_, n = row % N_;
    es[rl][j] = g_h[(((long)b*T_ + (T_-1))*N_ + n)*H_ + j];
    __syncthreads();
    if (j < 32) {
        float acc = 0.f;
#pragma unroll
        for (int k = 0; k < 64; k++) acc += es[rl][k] * w1[k*32 + j];
        g_av[row*32 + j] = acc;
    } else {
        int jj = j - 32;
        float acc = b1[jj];
#pragma unroll
        for (int k = 0; k < 64; k++) acc += es[rl][k] * w1[(64 + k)*32 + jj];
        g_cv[row*32 + jj] = acc;
    }
}

// ---------------- pairwise head: relu(a_i + c_j) -> LN -> dot -> sigmoid ----------------
__global__ void __launch_bounds__(256) k_head(
    float* __restrict__ out,
    const float* __restrict__ og, const float* __restrict__ ob,
    const float* __restrict__ w2, const float* __restrict__ b2) {
    __shared__ float sa[8][33], sc[32][33], sgw[32], sob[32];
    int tid = threadIdx.x;
    int b = blockIdx.z, i0 = blockIdx.y*8, j0 = blockIdx.x*32;
    {
        int il = tid >> 5, k = tid & 31;
        sa[il][k] = g_av[((long)b*N_ + i0 + il)*32 + k];
    }
#pragma unroll
    for (int q = 0; q < 4; q++) {
        int idx = q*256 + tid;
        int jl = idx >> 5, k = idx & 31;
        sc[jl][k] = g_cv[((long)b*N_ + j0 + jl)*32 + k];
    }
    if (tid < 32) { sgw[tid] = og[tid]*w2[tid]; sob[tid] = ob[tid]*w2[tid]; }
    __syncthreads();
    int jl = tid & 31, il = tid >> 5;
    float p[32]; float sum = 0.f;
#pragma unroll
    for (int k = 0; k < 32; k++) { p[k] = fmaxf(sa[il][k] + sc[jl][k], 0.f); sum += p[k]; }
    float m = sum * (1.f/32.f);
    float ss = 0.f, dot = 0.f, kc = 0.f;
#pragma unroll
    for (int k = 0; k < 32; k++) {
        float d = p[k] - m;
        ss  += d*d;
        dot += d*sgw[k];
        kc  += sob[k];
    }
    float logit = dot * rsqrtf(ss*(1.f/32.f) + EPS_) + kc + b2[0];
    out[((long)b*N_ + (i0 + il))*N_ + j0 + jl] = 1.f / (1.f + __expf(-logit));
}

// ---------------- orchestration ----------------
extern "C" void kernel_launch(void* const* d_in, const int* in_sizes, int n_in,
                              void* d_out, int out_size) {
    const float* x   = (const float*)d_in[0];
    const int*   ei  = (const int*)  d_in[1];
    const float* ew  = (const float*)d_in[2];
    const float* ipw = (const float*)d_in[3];
    const float* ipb = (const float*)d_in[4];
    const float* tcw = (const float*)d_in[5];
    const float* tcb = (const float*)d_in[6];
    const float* chw = (const float*)d_in[7];
    const float* chb = (const float*)d_in[8];
    const float* bng = (const float*)d_in[9];
    const float* bnb = (const float*)d_in[10];
    const float* lng = (const float*)d_in[11];
    const float* lnb = (const float*)d_in[12];
    const float* o1w = (const float*)d_in[13];
    const float* o1b = (const float*)d_in[14];
    const float* olg = (const float*)d_in[15];
    const float* olb = (const float*)d_in[16];
    const float* o2w = (const float*)d_in[17];
    const float* o2b = (const float*)d_in[18];
    float* out = (float*)d_out;

    float *p_h, *p_z1, *p_z2, *p_z3, *p_wT;
    cudaGetSymbolAddress((void**)&p_h,  g_h);
    cudaGetSymbolAddress((void**)&p_z1, g_z1);
    cudaGetSymbolAddress((void**)&p_z2, g_z2);
    cudaGetSymbolAddress((void**)&p_z3, g_z3);
    cudaGetSymbolAddress((void**)&p_wT, g_wT);

    k_prep0<<<3, 256>>>();
    k_prep1<<<96, 256>>>(ei, ew);
    k_scan<<<1, 1024>>>();
    k_scatter<<<96, 256>>>(ei, ew);
    k_wt<<<576, 256>>>(tcw);
    k_inproj<<<9216, 256>>>(x, ipw, ipb);

    for (int l = 0; l < 2; l++) {
        k_tconv<<<576, 256>>>(p_h,  p_z1, p_wT + (l*2 + 0)*36864, tcb + (l*2 + 0)*192);
        k_lhat<<<768, 256>>>(p_z1, p_z2);
        k_cheb<<<576, 256>>>(p_z1, p_z2, p_z3, chw + l*2*4096, chb + l*64);
        k_tconv<<<576, 256>>>(p_z3, p_z1, p_wT + (l*2 + 1)*36864, tcb + (l*2 + 1)*192);
        k_bnstats<<<768, 256>>>(p_z1);
        k_bnln<<<4608, 256>>>(p_z1, bng + l*N_, bnb + l*N_, lng + l*64, lnb + l*64);
    }

    k_emb<<<768, 256>>>(o1w, o1b);
    dim3 hg(24, 96, 4);
    k_head<<<hg, 256>>>(out, olg, olb, o2w, o2b);
}

// round 2
// speedup vs baseline: 1.0048x; 1.0048x over previous
#include <cuda_runtime.h>
#include <math.h>

#define B_ 4
#define T_ 12
#define N_ 768
#define F_ 32
#define H_ 64
#define E_ 24576
#define M_ (B_*T_*N_)
#define EPS_ 1e-5f

typedef unsigned long long u64;

// packed fp32x2 fma: d = a*b + c (lane-wise fp32, exact)
#define FMA2(d, a, b, c) \
    asm("fma.rn.f32x2 %0, %1, %2, %3;" : "=l"(d) : "l"(a), "l"(b), "l"(c))
#define PACK2_DUP(d, s) \
    asm("mov.b64 %0, {%1, %1};" : "=l"(d) : "f"(s))
#define UNPACK2(lo, hi, v) \
    asm("mov.b64 {%0, %1}, %2;" : "=f"(lo), "=f"(hi) : "l"(v))

// ---------------- device scratch (module-load allocated, allowed) ----------------
__device__ float g_h [M_*H_];
__device__ float g_z1[M_*H_];
__device__ float g_z2[M_*H_];
__device__ float g_z3[M_*H_];
__device__ float g_wT[4*3*3*H_*H_];      // [ls][kt][g][hi][ho]
__device__ float g_deg[N_];
__device__ int   g_cnt[N_];
__device__ int   g_rowptr[N_+1];
__device__ int   g_cursor[N_];
__device__ float g_dinv[N_];
__device__ int   g_ccol[E_];
__device__ float g_cw[E_];
__device__ float g_mu[N_];
__device__ float g_rstdv[N_];
__device__ float g_av[B_*N_*32];
__device__ float g_cv[B_*N_*32];

// ---------------- graph preprocessing ----------------
__global__ void k_prep0() {
    int i = blockIdx.x*256 + threadIdx.x;
    if (i < N_) { g_deg[i] = 0.f; g_cnt[i] = 0; }
}

__global__ void k_prep1(const int* __restrict__ ei, const float* __restrict__ ew) {
    int e = blockIdx.x*256 + threadIdx.x;
    if (e < E_) {
        int r = ei[e];
        atomicAdd(&g_deg[r], ew[e]);
        atomicAdd(&g_cnt[r], 1);
    }
}

__global__ void k_scan() {   // single block, 1024 threads
    __shared__ int s[1024];
    int tid = threadIdx.x;
    s[tid] = (tid < N_) ? g_cnt[tid] : 0;
    if (tid < N_) {
        float d = g_deg[tid];
        g_dinv[tid] = (d > 0.f) ? rsqrtf(fmaxf(d, 1e-12f)) : 0.f;
    }
    __syncthreads();
    for (int off = 1; off < 1024; off <<= 1) {
        int v = (tid >= off) ? s[tid-off] : 0;
        __syncthreads();
        s[tid] += v;
        __syncthreads();
    }
    if (tid < N_) {
        int ex = (tid == 0) ? 0 : s[tid-1];
        g_rowptr[tid] = ex;
        g_cursor[tid] = ex;
    }
    if (tid == N_-1) g_rowptr[N_] = s[N_-1];
}

__global__ void k_scatter(const int* __restrict__ ei, const float* __restrict__ ew) {
    int e = blockIdx.x*256 + threadIdx.x;
    if (e < E_) {
        int r = ei[e], c = ei[E_+e];
        int pos = atomicAdd(&g_cursor[r], 1);
        g_ccol[pos] = c;
        g_cw[pos] = -g_dinv[r] * ew[e] * g_dinv[c];
    }
}

// transpose tc_w (L,2,3,ho,hi,kt) -> g_wT [ls][kt][g][hi][ho]
__global__ void k_wt(const float* __restrict__ w) {
    int idx = blockIdx.x*256 + threadIdx.x;   // 0..147455
    int ho = idx & 63;
    int hi = (idx >> 6) & 63;
    int g  = (idx >> 12) % 3;
    int kt = (idx / 12288) % 3;
    int ls = idx / 36864;
    g_wT[idx] = w[(((ls*3 + g)*64 + ho)*64 + hi)*3 + kt];
}

// ---------------- input projection ----------------
__global__ void __launch_bounds__(256) k_inproj(const float* __restrict__ x,
    const float* __restrict__ pw, const float* __restrict__ pb) {
    __shared__ float xs[4][32];
    int rl = threadIdx.x >> 6, j = threadIdx.x & 63;
    int row = blockIdx.x*4 + rl;
    if (j < 32) xs[rl][j] = x[(long)row*F_ + j];
    __syncthreads();
    float acc = pb[j];
#pragma unroll
    for (int f = 0; f < 32; f++) acc += xs[rl][f] * pw[f*64 + j];
    g_h[(long)row*H_ + j] = acc;
}

// ---------------- gated temporal conv (3 shifted GEMMs, fused gates, f32x2) ----------------
__global__ void __launch_bounds__(256) k_tconv(
    const float* __restrict__ in, float* __restrict__ out,
    const float* __restrict__ wT, const float* __restrict__ bias) {
    __shared__ __align__(16) float As[64][64];
    __shared__ __align__(16) float Ws[3][32][64];
    const int tid  = threadIdx.x;
    const int r0   = blockIdx.x * 64;
    const int t    = (r0 / N_) % T_;
    const int col4 = (tid & 15) * 4;
    const int row4 = (tid >> 4) * 4;
    const int lrow = tid >> 4;
    const int lhi  = (tid & 15) * 4;

    u64 acc2[3][4][2];   // [gate][i][j-pair], f32x2 lanes = (col4+2jp, col4+2jp+1)
#pragma unroll
    for (int g = 0; g < 3; g++)
#pragma unroll
        for (int i = 0; i < 4; i++)
#pragma unroll
            for (int jp = 0; jp < 2; jp++) acc2[g][i][jp] = 0ull;

    for (int kt = 0; kt < 3; kt++) {
        const int dt = kt - 1;
        const bool valid = ((unsigned)(t + dt)) < (unsigned)T_;
        __syncthreads();
        const float* src = in + (long)(r0 + dt*N_) * H_;
#pragma unroll
        for (int rr = 0; rr < 4; rr++) {
            int row = lrow + rr*16;
            float4 v = make_float4(0.f, 0.f, 0.f, 0.f);
            if (valid) v = *(const float4*)(src + row*H_ + lhi);
            *(float4*)(&As[row][lhi]) = v;
        }
        for (int hic = 0; hic < 64; hic += 32) {
            __syncthreads();
#pragma unroll
            for (int q = 0; q < 6; q++) {
                int idx = q*256 + tid;       // 0..1535 float4 units
                int ho4 = (idx & 15) * 4;
                int hig = idx >> 4;          // 0..95
                int g  = hig >> 5;
                int hr = hig & 31;
                *(float4*)(&Ws[g][hr][ho4]) =
                    *(const float4*)(wT + ((kt*3 + g)*64 + hic + hr)*64 + ho4);
            }
            __syncthreads();
#pragma unroll 8
            for (int hh = 0; hh < 32; hh++) {
                u64 avp[4];
#pragma unroll
                for (int i = 0; i < 4; i++) {
                    float a = As[row4+i][hic+hh];
                    PACK2_DUP(avp[i], a);
                }
#pragma unroll
                for (int g = 0; g < 3; g++) {
                    ulonglong2 w = *(const ulonglong2*)(&Ws[g][hh][col4]);
#pragma unroll
                    for (int i = 0; i < 4; i++) {
                        FMA2(acc2[g][i][0], avp[i], w.x, acc2[g][i][0]);
                        FMA2(acc2[g][i][1], avp[i], w.y, acc2[g][i][1]);
                    }
                }
            }
        }
    }
    // epilogue: relu(g0 * sigmoid(g1) + g2), biases per gate
#pragma unroll
    for (int i = 0; i < 4; i++) {
        float a0[4], a1[4], a2[4];
#pragma unroll
        for (int jp = 0; jp < 2; jp++) {
            UNPACK2(a0[jp*2], a0[jp*2+1], acc2[0][i][jp]);
            UNPACK2(a1[jp*2], a1[jp*2+1], acc2[1][i][jp]);
            UNPACK2(a2[jp*2], a2[jp*2+1], acc2[2][i][jp]);
        }
        float r[4];
#pragma unroll
        for (int j = 0; j < 4; j++) {
            int ho = col4 + j;
            float y0 = a0[j] + bias[ho];
            float y1 = a1[j] + bias[64 + ho];
            float y2 = a2[j] + bias[128 + ho];
            float s = 1.f / (1.f + __expf(-y1));
            r[j] = fmaxf(y0*s + y2, 0.f);
        }
        float4 o = make_float4(r[0], r[1], r[2], r[3]);
        *(float4*)(out + (long)(r0 + row4 + i)*H_ + col4) = o;
    }
}

// ---------------- Laplacian propagation (CSR gather) ----------------
__global__ void __launch_bounds__(256) k_lhat(const float* __restrict__ z, float* __restrict__ out) {
    const int n   = blockIdx.x;
    const int tid = threadIdx.x;
    const int h   = tid & 63;
    const int btg = tid >> 6;     // 0..3, each handles 12 (b,t) slices
    __shared__ int   s_col[256];
    __shared__ float s_w[256];
    const int e0 = g_rowptr[n], e1 = g_rowptr[n+1];
    float acc[12];
#pragma unroll
    for (int q = 0; q < 12; q++) acc[q] = 0.f;
    for (int base = e0; base < e1; base += 256) {
        int cnt = min(256, e1 - base);
        __syncthreads();
        if (tid < cnt) { s_col[tid] = g_ccol[base + tid]; s_w[tid] = g_cw[base + tid]; }
        __syncthreads();
        for (int e = 0; e < cnt; e++) {
            const float* zp = z + ((long)(btg*12)*N_ + s_col[e])*H_ + h;
            float w = s_w[e];
#pragma unroll
            for (int q = 0; q < 12; q++) acc[q] += w * zp[(long)q * N_ * H_];
        }
    }
#pragma unroll
    for (int q = 0; q < 12; q++)
        out[((long)(btg*12 + q)*N_ + n)*H_ + h] = acc[q];
}

// ---------------- cheb combine: relu(z0@th0 + z1@th1 + b) (f32x2) ----------------
__global__ void __launch_bounds__(256) k_cheb(
    const float* __restrict__ z0, const float* __restrict__ z1,
    float* __restrict__ out,
    const float* __restrict__ th, const float* __restrict__ cb) {
    __shared__ __align__(16) float As[2][64][64];
    __shared__ __align__(16) float Ws[2][16][64];
    const int tid  = threadIdx.x;
    const int r0   = blockIdx.x * 64;
    const int col4 = (tid & 15) * 4;
    const int row4 = (tid >> 4) * 4;
    const int lrow = tid >> 4;
    const int lhi  = (tid & 15) * 4;

    u64 acc2[4][2];
#pragma unroll
    for (int i = 0; i < 4; i++)
#pragma unroll
        for (int jp = 0; jp < 2; jp++) acc2[i][jp] = 0ull;

#pragma unroll
    for (int rr = 0; rr < 4; rr++) {
        int row = lrow + rr*16;
        *(float4*)(&As[0][row][lhi]) = *(const float4*)(z0 + (long)(r0 + row)*H_ + lhi);
        *(float4*)(&As[1][row][lhi]) = *(const float4*)(z1 + (long)(r0 + row)*H_ + lhi);
    }
    for (int hic = 0; hic < 64; hic += 16) {
        __syncthreads();
#pragma unroll
        for (int q = 0; q < 2; q++) {
            int idx = q*256 + tid;      // 0..511 float4 units
            int ho4 = (idx & 15) * 4;
            int rr  = idx >> 4;         // 0..31
            int k   = rr >> 4, hr = rr & 15;
            *(float4*)(&Ws[k][hr][ho4]) =
                *(const float4*)(th + (k*64 + hic + hr)*64 + ho4);
        }
        __syncthreads();
#pragma unroll
        for (int hh = 0; hh < 16; hh++) {
            u64 avp[4], bvp[4];
#pragma unroll
            for (int i = 0; i < 4; i++) {
                float a = As[0][row4+i][hic+hh];
                float b = As[1][row4+i][hic+hh];
                PACK2_DUP(avp[i], a);
                PACK2_DUP(bvp[i], b);
            }
            ulonglong2 w0 = *(const ulonglong2*)(&Ws[0][hh][col4]);
            ulonglong2 w1 = *(const ulonglong2*)(&Ws[1][hh][col4]);
#pragma unroll
            for (int i = 0; i < 4; i++) {
                FMA2(acc2[i][0], avp[i], w0.x, acc2[i][0]);
                FMA2(acc2[i][1], avp[i], w0.y, acc2[i][1]);
                FMA2(acc2[i][0], bvp[i], w1.x, acc2[i][0]);
                FMA2(acc2[i][1], bvp[i], w1.y, acc2[i][1]);
            }
        }
    }
#pragma unroll
    for (int i = 0; i < 4; i++) {
        float r[4];
#pragma unroll
        for (int jp = 0; jp < 2; jp++) UNPACK2(r[jp*2], r[jp*2+1], acc2[i][jp]);
        float4 o;
        o.x = fmaxf(r[0] + cb[col4+0], 0.f);
        o.y = fmaxf(r[1] + cb[col4+1], 0.f);
        o.z = fmaxf(r[2] + cb[col4+2], 0.f);
        o.w = fmaxf(r[3] + cb[col4+3], 0.f);
        *(float4*)(out + (long)(r0 + row4 + i)*H_ + col4) = o;
    }
}

// ---------------- BatchNorm stats per node (double accumulation) ----------------
__global__ void __launch_bounds__(256) k_bnstats(const float* __restrict__ z) {
    const int n = blockIdx.x;
    const int tid = threadIdx.x;
    double s = 0.0, ss = 0.0;
    for (int idx = tid; idx < B_*T_*H_; idx += 256) {
        int bt = idx >> 6, h = idx & 63;
        float v = z[((long)bt*N_ + n)*H_ + h];
        s += v; ss += (double)v * v;
    }
    __shared__ double sh_s[8], sh_ss[8];
#pragma unroll
    for (int off = 16; off; off >>= 1) {
        s  += __shfl_xor_sync(0xffffffffu, s, off);
        ss += __shfl_xor_sync(0xffffffffu, ss, off);
    }
    int w = tid >> 5, l = tid & 31;
    if (l == 0) { sh_s[w] = s; sh_ss[w] = ss; }
    __syncthreads();
    if (tid == 0) {
        double ts = 0.0, tss = 0.0;
        for (int q = 0; q < 8; q++) { ts += sh_s[q]; tss += sh_ss[q]; }
        double mu  = ts / (double)(B_*T_*H_);
        double var = tss / (double)(B_*T_*H_) - mu*mu;
        g_mu[n]    = (float)mu;
        g_rstdv[n] = rsqrtf((float)var + EPS_);
    }
}

// ---------------- BN apply + LayerNorm + residual into g_h ----------------
__global__ void __launch_bounds__(256) k_bnln(
    const float* __restrict__ z,
    const float* __restrict__ bng, const float* __restrict__ bnb,
    const float* __restrict__ lng, const float* __restrict__ lnb) {
    int warp = threadIdx.x >> 5, lane = threadIdx.x & 31;
    int row = blockIdx.x*8 + warp;
    int n = row % N_;
    float mu = g_mu[n], rs = g_rstdv[n];
    float bg = bng[n] * rs, bb = bnb[n];
    float v0 = z[(long)row*H_ + lane];
    float v1 = z[(long)row*H_ + lane + 32];
    float u0 = (v0 - mu)*bg + bb;
    float u1 = (v1 - mu)*bg + bb;
    float sm = u0 + u1;
#pragma unroll
    for (int off = 16; off; off >>= 1) sm += __shfl_xor_sync(0xffffffffu, sm, off);
    float m = sm * (1.f/64.f);
    float d0 = u0 - m, d1 = u1 - m;
    float q = d0*d0 + d1*d1;
#pragma unroll
    for (int off = 16; off; off >>= 1) q += __shfl_xor_sync(0xffffffffu, q, off);
    float r = rsqrtf(q*(1.f/64.f) + EPS_);
    float* hp = g_h + (long)row*H_;
    hp[lane]      += d0*r*lng[lane]      + lnb[lane];
    hp[lane + 32] += d1*r*lng[lane + 32] + lnb[lane + 32];
}

// ---------------- head: a = emb@W1[:64], c = emb@W1[64:] + b1 ----------------
__global__ void __launch_bounds__(256) k_emb(const float* __restrict__ w1, const float* __restrict__ b1) {
    __shared__ float es[4][64];
    int rl = threadIdx.x >> 6, j = threadIdx.x & 63;
    int row = blockIdx.x*4 + rl;          // 0..3071
    int b = row / N_, n = row % N_;
    es[rl][j] = g_h[(((long)b*T_ + (T_-1))*N_ + n)*H_ + j];
    __syncthreads();
    if (j < 32) {
        float acc = 0.f;
#pragma unroll
        for (int k = 0; k < 64; k++) acc += es[rl][k] * w1[k*32 + j];
        g_av[row*32 + j] = acc;
    } else {
        int jj = j - 32;
        float acc = b1[jj];
#pragma unroll
        for (int k = 0; k < 64; k++) acc += es[rl][k] * w1[(64 + k)*32 + jj];
        g_cv[row*32 + jj] = acc;
    }
}

// ---------------- pairwise head: relu(a_i + c_j) -> LN -> dot -> sigmoid ----------------
__global__ void __launch_bounds__(256) k_head(
    float* __restrict__ out,
    const float* __restrict__ og, const float* __restrict__ ob,
    const float* __restrict__ w2, const float* __restrict__ b2) {
    __shared__ float sa[8][33], sc[32][33], sgw[32], sob[32];
    int tid = threadIdx.x;
    int b = blockIdx.z, i0 = blockIdx.y*8, j0 = blockIdx.x*32;
    {
        int il = tid >> 5, k = tid & 31;
        sa[il][k] = g_av[((long)b*N_ + i0 + il)*32 + k];
    }
#pragma unroll
    for (int q = 0; q < 4; q++) {
        int idx = q*256 + tid;
        int jl = idx >> 5, k = idx & 31;
        sc[jl][k] = g_cv[((long)b*N_ + j0 + jl)*32 + k];
    }
    if (tid < 32) { sgw[tid] = og[tid]*w2[tid]; sob[tid] = ob[tid]*w2[tid]; }
    __syncthreads();
    int jl = tid & 31, il = tid >> 5;
    float p[32]; float sum = 0.f;
#pragma unroll
    for (int k = 0; k < 32; k++) { p[k] = fmaxf(sa[il][k] + sc[jl][k], 0.f); sum += p[k]; }
    float m = sum * (1.f/32.f);
    float ss = 0.f, dot = 0.f, kc = 0.f;
#pragma unroll
    for (int k = 0; k < 32; k++) {
        float d = p[k] - m;
        ss  += d*d;
        dot += d*sgw[k];
        kc  += sob[k];
    }
    float logit = dot * rsqrtf(ss*(1.f/32.f) + EPS_) + kc + b2[0];
    out[((long)b*N_ + (i0 + il))*N_ + j0 + jl] = 1.f / (1.f + __expf(-logit));
}

// ---------------- orchestration ----------------
extern "C" void kernel_launch(void* const* d_in, const int* in_sizes, int n_in,
                              void* d_out, int out_size) {
    const float* x   = (const float*)d_in[0];
    const int*   ei  = (const int*)  d_in[1];
    const float* ew  = (const float*)d_in[2];
    const float* ipw = (const float*)d_in[3];
    const float* ipb = (const float*)d_in[4];
    const float* tcw = (const float*)d_in[5];
    const float* tcb = (const float*)d_in[6];
    const float* chw = (const float*)d_in[7];
    const float* chb = (const float*)d_in[8];
    const float* bng = (const float*)d_in[9];
    const float* bnb = (const float*)d_in[10];
    const float* lng = (const float*)d_in[11];
    const float* lnb = (const float*)d_in[12];
    const float* o1w = (const float*)d_in[13];
    const float* o1b = (const float*)d_in[14];
    const float* olg = (const float*)d_in[15];
    const float* olb = (const float*)d_in[16];
    const float* o2w = (const float*)d_in[17];
    const float* o2b = (const float*)d_in[18];
    float* out = (float*)d_out;

    float *p_h, *p_z1, *p_z2, *p_z3, *p_wT;
    cudaGetSymbolAddress((void**)&p_h,  g_h);
    cudaGetSymbolAddress((void**)&p_z1, g_z1);
    cudaGetSymbolAddress((void**)&p_z2, g_z2);
    cudaGetSymbolAddress((void**)&p_z3, g_z3);
    cudaGetSymbolAddress((void**)&p_wT, g_wT);

    k_prep0<<<3, 256>>>();
    k_prep1<<<96, 256>>>(ei, ew);
    k_scan<<<1, 1024>>>();
    k_scatter<<<96, 256>>>(ei, ew);
    k_wt<<<576, 256>>>(tcw);
    k_inproj<<<9216, 256>>>(x, ipw, ipb);

    for (int l = 0; l < 2; l++) {
        k_tconv<<<576, 256>>>(p_h,  p_z1, p_wT + (l*2 + 0)*36864, tcb + (l*2 + 0)*192);
        k_lhat<<<768, 256>>>(p_z1, p_z2);
        k_cheb<<<576, 256>>>(p_z1, p_z2, p_z3, chw + l*2*4096, chb + l*64);
        k_tconv<<<576, 256>>>(p_z3, p_z1, p_wT + (l*2 + 1)*36864, tcb + (l*2 + 1)*192);
        k_bnstats<<<768, 256>>>(p_z1);
        k_bnln<<<4608, 256>>>(p_z1, bng + l*N_, bnb + l*N_, lng + l*64, lnb + l*64);
    }

    k_emb<<<768, 256>>>(o1w, o1b);
    dim3 hg(24, 96, 4);
    k_head<<<hg, 256>>>(out, olg, olb, o2w, o2b);
}

// round 3
// speedup vs baseline: 1.3772x; 1.3706x over previous
#include <cuda_runtime.h>
#include <math.h>

#define B_ 4
#define T_ 12
#define N_ 768
#define F_ 32
#define H_ 64
#define E_ 24576
#define M_ (B_*T_*N_)
#define EPS_ 1e-5f

#define CVT_TF32(u, f) asm("cvt.rna.tf32.f32 %0, %1;" : "=r"(u) : "f"(f))

#define MMA_TF32(d0,d1,d2,d3,a0,a1,a2,a3,b0,b1) \
    asm volatile("mma.sync.aligned.m16n8k8.row.col.f32.tf32.tf32.f32 " \
        "{%0,%1,%2,%3}, {%4,%5,%6,%7}, {%8,%9}, {%0,%1,%2,%3};" \
        : "+f"(d0),"+f"(d1),"+f"(d2),"+f"(d3) \
        : "r"(a0),"r"(a1),"r"(a2),"r"(a3),"r"(b0),"r"(b1))

// ---------------- device scratch ----------------
__device__ float    g_h [M_*H_];
__device__ float    g_z1[M_*H_];
__device__ float    g_z2[M_*H_];
__device__ float    g_z3[M_*H_];
__device__ unsigned g_wT[4*3*3*H_*H_];   // tf32 bits, [ls][kt][g][hi][ho]
__device__ unsigned g_chT[2*2*H_*H_];    // tf32 bits, [l][k*64+hi][ho]
__device__ float    g_deg[N_];
__device__ int      g_cnt[N_];
__device__ int      g_rowptr[N_+1];
__device__ int      g_cursor[N_];
__device__ float    g_dinv[N_];
__device__ int      g_ccol[E_];
__device__ float    g_cw[E_];
__device__ float    g_mu[N_];
__device__ float    g_rstdv[N_];
__device__ float    g_av[B_*N_*32];
__device__ float    g_cv[B_*N_*32];

// ---------------- graph preprocessing ----------------
__global__ void k_prep0() {
    int i = blockIdx.x*256 + threadIdx.x;
    if (i < N_) { g_deg[i] = 0.f; g_cnt[i] = 0; }
}

__global__ void k_prep1(const int* __restrict__ ei, const float* __restrict__ ew) {
    int e = blockIdx.x*256 + threadIdx.x;
    if (e < E_) {
        int r = ei[e];
        atomicAdd(&g_deg[r], ew[e]);
        atomicAdd(&g_cnt[r], 1);
    }
}

__global__ void k_scan() {
    __shared__ int s[1024];
    int tid = threadIdx.x;
    s[tid] = (tid < N_) ? g_cnt[tid] : 0;
    if (tid < N_) {
        float d = g_deg[tid];
        g_dinv[tid] = (d > 0.f) ? rsqrtf(fmaxf(d, 1e-12f)) : 0.f;
    }
    __syncthreads();
    for (int off = 1; off < 1024; off <<= 1) {
        int v = (tid >= off) ? s[tid-off] : 0;
        __syncthreads();
        s[tid] += v;
        __syncthreads();
    }
    if (tid < N_) {
        int ex = (tid == 0) ? 0 : s[tid-1];
        g_rowptr[tid] = ex;
        g_cursor[tid] = ex;
    }
    if (tid == N_-1) g_rowptr[N_] = s[N_-1];
}

__global__ void k_scatter(const int* __restrict__ ei, const float* __restrict__ ew) {
    int e = blockIdx.x*256 + threadIdx.x;
    if (e < E_) {
        int r = ei[e], c = ei[E_+e];
        int pos = atomicAdd(&g_cursor[r], 1);
        g_ccol[pos] = c;
        g_cw[pos] = -g_dinv[r] * ew[e] * g_dinv[c];
    }
}

// tc_w (L,2,3,ho,hi,kt) -> tf32 g_wT [ls][kt][g][hi][ho]
__global__ void k_wt(const float* __restrict__ w) {
    int idx = blockIdx.x*256 + threadIdx.x;   // 0..147455
    int ho = idx & 63;
    int hi = (idx >> 6) & 63;
    int g  = (idx >> 12) % 3;
    int kt = (idx / 12288) % 3;
    int ls = idx / 36864;
    float v = w[(((ls*3 + g)*64 + ho)*64 + hi)*3 + kt];
    unsigned u; CVT_TF32(u, v);
    g_wT[idx] = u;
}

// cheb_w (L,K,hi,ho) -> tf32 (same layout)
__global__ void k_cwt(const float* __restrict__ w) {
    int idx = blockIdx.x*256 + threadIdx.x;   // 0..16383
    float v = w[idx];
    unsigned u; CVT_TF32(u, v);
    g_chT[idx] = u;
}

// ---------------- input projection ----------------
__global__ void __launch_bounds__(256) k_inproj(const float* __restrict__ x,
    const float* __restrict__ pw, const float* __restrict__ pb) {
    __shared__ float xs[4][32];
    int rl = threadIdx.x >> 6, j = threadIdx.x & 63;
    int row = blockIdx.x*4 + rl;
    if (j < 32) xs[rl][j] = x[(long)row*F_ + j];
    __syncthreads();
    float acc = pb[j];
#pragma unroll
    for (int f = 0; f < 32; f++) acc += xs[rl][f] * pw[f*64 + j];
    g_h[(long)row*H_ + j] = acc;
}

// ---------------- gated temporal conv: tf32 mma.sync ----------------
// block: 64 rows x (3 gates x 64) outs, K=192 (3 kt x 64)
// smem: sA[64][68] tf32, sW[192][68] tf32; epilogue overlay sE[64][196] f32
__global__ void __launch_bounds__(256) k_tconv(
    const float* __restrict__ in, float* __restrict__ out,
    const unsigned* __restrict__ wT, const float* __restrict__ bias) {
    extern __shared__ __align__(16) unsigned smem[];
    unsigned* sA = smem;               // 64*68
    unsigned* sW = smem + 64*68;       // 192*68
    float*    sE = (float*)smem;       // 64*196 (epilogue)

    const int tid  = threadIdx.x;
    const int lane = tid & 31;
    const int w    = tid >> 5;
    const int wm   = w >> 2;          // 0..1
    const int wn   = w & 3;           // 0..3
    const int r0   = blockIdx.x * 64;
    const int t    = (r0 / N_) % T_;
    const int lrow = tid >> 4;        // 0..15
    const int lhi  = (tid & 15) * 4;

    const int aBase = (wm*32 + (lane>>2))*68 + (lane&3);
    int bOff[6];
#pragma unroll
    for (int j = 0; j < 6; j++) {
        int colj = wn*48 + j*8;
        int g = colj >> 6, nin = colj & 63;
        bOff[j] = ((g<<6) + (lane&3))*68 + nin + (lane>>2);
    }

    float d[2][6][4];
#pragma unroll
    for (int mi = 0; mi < 2; mi++)
#pragma unroll
        for (int j = 0; j < 6; j++)
#pragma unroll
            for (int q = 0; q < 4; q++) d[mi][j][q] = 0.f;

    for (int kt = 0; kt < 3; kt++) {
        __syncthreads();
        // fill weights: 3*64*64 tf32 words
        const uint4* wsrc = (const uint4*)(wT + kt*3*4096);
#pragma unroll
        for (int q = 0; q < 12; q++) {
            int idx = q*256 + tid;          // 0..3071 uint4 units
            int ho4 = (idx & 15) * 4;
            int ghi = idx >> 4;             // 0..191
            *(uint4*)(sW + ghi*68 + ho4) = wsrc[idx];
        }
        // fill A with cvt
        const int dt = kt - 1;
        const bool valid = ((unsigned)(t + dt)) < (unsigned)T_;
        const float* src = in + (long)(r0 + dt*N_) * H_;
#pragma unroll
        for (int rr = 0; rr < 4; rr++) {
            int row = lrow + rr*16;
            float4 v = make_float4(0.f,0.f,0.f,0.f);
            if (valid) v = *(const float4*)(src + row*H_ + lhi);
            uint4 u;
            CVT_TF32(u.x, v.x); CVT_TF32(u.y, v.y);
            CVT_TF32(u.z, v.z); CVT_TF32(u.w, v.w);
            *(uint4*)(sA + row*68 + lhi) = u;
        }
        __syncthreads();
#pragma unroll
        for (int ks = 0; ks < 8; ks++) {
            const int ka = aBase + ks*8;
            const int kb = ks*8*68;
            unsigned a[2][4];
#pragma unroll
            for (int mi = 0; mi < 2; mi++) {
                int base = ka + mi*16*68;
                a[mi][0] = sA[base];
                a[mi][1] = sA[base + 8*68];
                a[mi][2] = sA[base + 4];
                a[mi][3] = sA[base + 8*68 + 4];
            }
#pragma unroll
            for (int j = 0; j < 6; j++) {
                unsigned b0 = sW[bOff[j] + kb];
                unsigned b1 = sW[bOff[j] + kb + 4*68];
#pragma unroll
                for (int mi = 0; mi < 2; mi++)
                    MMA_TF32(d[mi][j][0], d[mi][j][1], d[mi][j][2], d[mi][j][3],
                             a[mi][0], a[mi][1], a[mi][2], a[mi][3], b0, b1);
            }
        }
    }
    // park accumulators in smem for cross-warp gate combine
    __syncthreads();
#pragma unroll
    for (int mi = 0; mi < 2; mi++)
#pragma unroll
        for (int j = 0; j < 6; j++) {
            int r = wm*32 + mi*16 + (lane>>2);
            int c = wn*48 + j*8 + 2*(lane&3);
            *(float2*)&sE[r*196 + c]     = make_float2(d[mi][j][0], d[mi][j][1]);
            *(float2*)&sE[(r+8)*196 + c] = make_float2(d[mi][j][2], d[mi][j][3]);
        }
    __syncthreads();
    // combine: relu(g0*sigmoid(g1)+g2)
    const int col4 = (tid & 15) * 4;
    const int row4 = (tid >> 4) * 4;
#pragma unroll
    for (int i = 0; i < 4; i++) {
        int row = row4 + i;
        float r[4];
#pragma unroll
        for (int jj = 0; jj < 4; jj++) {
            int ho = col4 + jj;
            float y0 = sE[row*196 + ho]        + bias[ho];
            float y1 = sE[row*196 + 64 + ho]   + bias[64 + ho];
            float y2 = sE[row*196 + 128 + ho]  + bias[128 + ho];
            float s = 1.f / (1.f + __expf(-y1));
            r[jj] = fmaxf(y0*s + y2, 0.f);
        }
        *(float4*)(out + (long)(r0 + row)*H_ + col4) = make_float4(r[0],r[1],r[2],r[3]);
    }
}

// ---------------- Laplacian propagation (CSR gather) ----------------
__global__ void __launch_bounds__(256) k_lhat(const float* __restrict__ z, float* __restrict__ out) {
    const int n   = blockIdx.x;
    const int tid = threadIdx.x;
    const int h   = tid & 63;
    const int btg = tid >> 6;
    __shared__ int   s_col[256];
    __shared__ float s_w[256];
    const int e0 = g_rowptr[n], e1 = g_rowptr[n+1];
    float acc[12];
#pragma unroll
    for (int q = 0; q < 12; q++) acc[q] = 0.f;
    for (int base = e0; base < e1; base += 256) {
        int cnt = min(256, e1 - base);
        __syncthreads();
        if (tid < cnt) { s_col[tid] = g_ccol[base + tid]; s_w[tid] = g_cw[base + tid]; }
        __syncthreads();
        for (int e = 0; e < cnt; e++) {
            const float* zp = z + ((long)(btg*12)*N_ + s_col[e])*H_ + h;
            float w = s_w[e];
#pragma unroll
            for (int q = 0; q < 12; q++) acc[q] += w * zp[(long)q * N_ * H_];
        }
    }
#pragma unroll
    for (int q = 0; q < 12; q++)
        out[((long)(btg*12 + q)*N_ + n)*H_ + h] = acc[q];
}

// ---------------- cheb combine via tf32 mma: relu([z0|z1]@[th0;th1] + b) ----------------
// smem: sA[64][132] tf32, sW[128][68] tf32
__global__ void __launch_bounds__(256) k_cheb(
    const float* __restrict__ z0, const float* __restrict__ z1,
    float* __restrict__ out,
    const unsigned* __restrict__ th, const float* __restrict__ cb) {
    extern __shared__ __align__(16) unsigned smem[];
    unsigned* sA = smem;               // 64*132
    unsigned* sW = smem + 64*132;      // 128*68

    const int tid  = threadIdx.x;
    const int lane = tid & 31;
    const int w    = tid >> 5;
    const int wm   = w >> 2;          // 0..1
    const int wn   = w & 3;           // 0..3
    const int r0   = blockIdx.x * 64;
    const int lrow = tid >> 4;
    const int lhi  = (tid & 15) * 4;

    // fill A = [z0 | z1] (cvt to tf32)
#pragma unroll
    for (int rr = 0; rr < 4; rr++) {
        int row = lrow + rr*16;
        float4 v0 = *(const float4*)(z0 + (long)(r0 + row)*H_ + lhi);
        float4 v1 = *(const float4*)(z1 + (long)(r0 + row)*H_ + lhi);
        uint4 u0, u1;
        CVT_TF32(u0.x, v0.x); CVT_TF32(u0.y, v0.y); CVT_TF32(u0.z, v0.z); CVT_TF32(u0.w, v0.w);
        CVT_TF32(u1.x, v1.x); CVT_TF32(u1.y, v1.y); CVT_TF32(u1.z, v1.z); CVT_TF32(u1.w, v1.w);
        *(uint4*)(sA + row*132 + lhi)      = u0;
        *(uint4*)(sA + row*132 + 64 + lhi) = u1;
    }
    // fill W: 128x64 tf32 words
    const uint4* wsrc = (const uint4*)th;
#pragma unroll
    for (int q = 0; q < 8; q++) {
        int idx = q*256 + tid;         // 0..2047 uint4 units
        int ho4 = (idx & 15) * 4;
        int kr  = idx >> 4;            // 0..127
        *(uint4*)(sW + kr*68 + ho4) = wsrc[idx];
    }
    __syncthreads();

    const int aBase = (wm*32 + (lane>>2))*132 + (lane&3);
    int bOff[2];
#pragma unroll
    for (int j = 0; j < 2; j++)
        bOff[j] = (lane&3)*68 + wn*16 + j*8 + (lane>>2);

    float d[2][2][4];
#pragma unroll
    for (int mi = 0; mi < 2; mi++)
#pragma unroll
        for (int j = 0; j < 2; j++)
#pragma unroll
            for (int q = 0; q < 4; q++) d[mi][j][q] = 0.f;

#pragma unroll
    for (int ks = 0; ks < 16; ks++) {
        const int ka = aBase + ks*8;
        const int kb = ks*8*68;
        unsigned a[2][4];
#pragma unroll
        for (int mi = 0; mi < 2; mi++) {
            int base = ka + mi*16*132;
            a[mi][0] = sA[base];
            a[mi][1] = sA[base + 8*132];
            a[mi][2] = sA[base + 4];
            a[mi][3] = sA[base + 8*132 + 4];
        }
#pragma unroll
        for (int j = 0; j < 2; j++) {
            unsigned b0 = sW[bOff[j] + kb];
            unsigned b1 = sW[bOff[j] + kb + 4*68];
#pragma unroll
            for (int mi = 0; mi < 2; mi++)
                MMA_TF32(d[mi][j][0], d[mi][j][1], d[mi][j][2], d[mi][j][3],
                         a[mi][0], a[mi][1], a[mi][2], a[mi][3], b0, b1);
        }
    }
    // direct epilogue
#pragma unroll
    for (int mi = 0; mi < 2; mi++)
#pragma unroll
        for (int j = 0; j < 2; j++) {
            int r = wm*32 + mi*16 + (lane>>2);
            int c = wn*16 + j*8 + 2*(lane&3);
            float b0 = cb[c], b1 = cb[c+1];
            *(float2*)(out + (long)(r0 + r)*H_ + c) =
                make_float2(fmaxf(d[mi][j][0] + b0, 0.f), fmaxf(d[mi][j][1] + b1, 0.f));
            *(float2*)(out + (long)(r0 + r + 8)*H_ + c) =
                make_float2(fmaxf(d[mi][j][2] + b0, 0.f), fmaxf(d[mi][j][3] + b1, 0.f));
        }
}

// ---------------- BatchNorm stats per node ----------------
__global__ void __launch_bounds__(256) k_bnstats(const float* __restrict__ z) {
    const int n = blockIdx.x;
    const int tid = threadIdx.x;
    double s = 0.0, ss = 0.0;
    for (int idx = tid; idx < B_*T_*H_; idx += 256) {
        int bt = idx >> 6, h = idx & 63;
        float v = z[((long)bt*N_ + n)*H_ + h];
        s += v; ss += (double)v * v;
    }
    __shared__ double sh_s[8], sh_ss[8];
#pragma unroll
    for (int off = 16; off; off >>= 1) {
        s  += __shfl_xor_sync(0xffffffffu, s, off);
        ss += __shfl_xor_sync(0xffffffffu, ss, off);
    }
    int wq = tid >> 5, l = tid & 31;
    if (l == 0) { sh_s[wq] = s; sh_ss[wq] = ss; }
    __syncthreads();
    if (tid == 0) {
        double ts = 0.0, tss = 0.0;
        for (int q = 0; q < 8; q++) { ts += sh_s[q]; tss += sh_ss[q]; }
        double mu  = ts / (double)(B_*T_*H_);
        double var = tss / (double)(B_*T_*H_) - mu*mu;
        g_mu[n]    = (float)mu;
        g_rstdv[n] = rsqrtf((float)var + EPS_);
    }
}

// ---------------- BN apply + LayerNorm + residual ----------------
__global__ void __launch_bounds__(256) k_bnln(
    const float* __restrict__ z,
    const float* __restrict__ bng, const float* __restrict__ bnb,
    const float* __restrict__ lng, const float* __restrict__ lnb) {
    int warp = threadIdx.x >> 5, lane = threadIdx.x & 31;
    int row = blockIdx.x*8 + warp;
    int n = row % N_;
    float mu = g_mu[n], rs = g_rstdv[n];
    float bg = bng[n] * rs, bb = bnb[n];
    float v0 = z[(long)row*H_ + lane];
    float v1 = z[(long)row*H_ + lane + 32];
    float u0 = (v0 - mu)*bg + bb;
    float u1 = (v1 - mu)*bg + bb;
    float sm = u0 + u1;
#pragma unroll
    for (int off = 16; off; off >>= 1) sm += __shfl_xor_sync(0xffffffffu, sm, off);
    float m = sm * (1.f/64.f);
    float d0 = u0 - m, d1 = u1 - m;
    float q = d0*d0 + d1*d1;
#pragma unroll
    for (int off = 16; off; off >>= 1) q += __shfl_xor_sync(0xffffffffu, q, off);
    float r = rsqrtf(q*(1.f/64.f) + EPS_);
    float* hp = g_h + (long)row*H_;
    hp[lane]      += d0*r*lng[lane]      + lnb[lane];
    hp[lane + 32] += d1*r*lng[lane + 32] + lnb[lane + 32];
}

// ---------------- head: a = emb@W1[:64], c = emb@W1[64:] + b1 ----------------
__global__ void __launch_bounds__(256) k_emb(const float* __restrict__ w1, const float* __restrict__ b1) {
    __shared__ float es[4][64];
    int rl = threadIdx.x >> 6, j = threadIdx.x & 63;
    int row = blockIdx.x*4 + rl;
    int b = row / N_, n = row % N_;
    es[rl][j] = g_h[(((long)b*T_ + (T_-1))*N_ + n)*H_ + j];
    __syncthreads();
    if (j < 32) {
        float acc = 0.f;
#pragma unroll
        for (int k = 0; k < 64; k++) acc += es[rl][k] * w1[k*32 + j];
        g_av[row*32 + j] = acc;
    } else {
        int jj = j - 32;
        float acc = b1[jj];
#pragma unroll
        for (int k = 0; k < 64; k++) acc += es[rl][k] * w1[(64 + k)*32 + jj];
        g_cv[row*32 + jj] = acc;
    }
}

// ---------------- pairwise head ----------------
__global__ void __launch_bounds__(256) k_head(
    float* __restrict__ out,
    const float* __restrict__ og, const float* __restrict__ ob,
    const float* __restrict__ w2, const float* __restrict__ b2) {
    __shared__ float sa[8][33], sc[32][33], sgw[32], sob[32];
    int tid = threadIdx.x;
    int b = blockIdx.z, i0 = blockIdx.y*8, j0 = blockIdx.x*32;
    {
        int il = tid >> 5, k = tid & 31;
        sa[il][k] = g_av[((long)b*N_ + i0 + il)*32 + k];
    }
#pragma unroll
    for (int q = 0; q < 4; q++) {
        int idx = q*256 + tid;
        int jl = idx >> 5, k = idx & 31;
        sc[jl][k] = g_cv[((long)b*N_ + j0 + jl)*32 + k];
    }
    if (tid < 32) { sgw[tid] = og[tid]*w2[tid]; sob[tid] = ob[tid]*w2[tid]; }
    __syncthreads();
    int jl = tid & 31, il = tid >> 5;
    float p[32]; float sum = 0.f;
#pragma unroll
    for (int k = 0; k < 32; k++) { p[k] = fmaxf(sa[il][k] + sc[jl][k], 0.f); sum += p[k]; }
    float m = sum * (1.f/32.f);
    float ss = 0.f, dot = 0.f, kc = 0.f;
#pragma unroll
    for (int k = 0; k < 32; k++) {
        float d = p[k] - m;
        ss  += d*d;
        dot += d*sgw[k];
        kc  += sob[k];
    }
    float logit = dot * rsqrtf(ss*(1.f/32.f) + EPS_) + kc + b2[0];
    out[((long)b*N_ + (i0 + il))*N_ + j0 + jl] = 1.f / (1.f + __expf(-logit));
}

// ---------------- orchestration ----------------
extern "C" void kernel_launch(void* const* d_in, const int* in_sizes, int n_in,
                              void* d_out, int out_size) {
    const float* x   = (const float*)d_in[0];
    const int*   ei  = (const int*)  d_in[1];
    const float* ew  = (const float*)d_in[2];
    const float* ipw = (const float*)d_in[3];
    const float* ipb = (const float*)d_in[4];
    const float* tcw = (const float*)d_in[5];
    const float* tcb = (const float*)d_in[6];
    const float* chw = (const float*)d_in[7];
    const float* chb = (const float*)d_in[8];
    const float* bng = (const float*)d_in[9];
    const float* bnb = (const float*)d_in[10];
    const float* lng = (const float*)d_in[11];
    const float* lnb = (const float*)d_in[12];
    const float* o1w = (const float*)d_in[13];
    const float* o1b = (const float*)d_in[14];
    const float* olg = (const float*)d_in[15];
    const float* olb = (const float*)d_in[16];
    const float* o2w = (const float*)d_in[17];
    const float* o2b = (const float*)d_in[18];
    float* out = (float*)d_out;

    const int TCONV_SMEM = (64*68 + 192*68) * 4;   // 69632
    const int CHEB_SMEM  = (64*132 + 128*68) * 4;  // 68608
    cudaFuncSetAttribute(k_tconv, cudaFuncAttributeMaxDynamicSharedMemorySize, TCONV_SMEM);
    cudaFuncSetAttribute(k_cheb,  cudaFuncAttributeMaxDynamicSharedMemorySize, CHEB_SMEM);

    float *p_h, *p_z1, *p_z2, *p_z3;
    unsigned *p_wT, *p_chT;
    cudaGetSymbolAddress((void**)&p_h,   g_h);
    cudaGetSymbolAddress((void**)&p_z1,  g_z1);
    cudaGetSymbolAddress((void**)&p_z2,  g_z2);
    cudaGetSymbolAddress((void**)&p_z3,  g_z3);
    cudaGetSymbolAddress((void**)&p_wT,  g_wT);
    cudaGetSymbolAddress((void**)&p_chT, g_chT);

    // order chosen so the profiled launch slot (index 3) is a k_tconv
    k_wt<<<576, 256>>>(tcw);                 // 0
    k_cwt<<<64, 256>>>(chw);                 // 1
    k_inproj<<<9216, 256>>>(x, ipw, ipb);    // 2
    k_tconv<<<576, 256, TCONV_SMEM>>>(p_h, p_z1, p_wT + 0*36864, tcb + 0*192);  // 3 (layer0 first)
    k_prep0<<<3, 256>>>();                   // 4
    k_prep1<<<96, 256>>>(ei, ew);            // 5
    k_scan<<<1, 1024>>>();                   // 6
    k_scatter<<<96, 256>>>(ei, ew);          // 7

    for (int l = 0; l < 2; l++) {
        if (l > 0)
            k_tconv<<<576, 256, TCONV_SMEM>>>(p_h, p_z1, p_wT + (l*2 + 0)*36864, tcb + (l*2 + 0)*192);
        k_lhat<<<768, 256>>>(p_z1, p_z2);
        k_cheb<<<576, 256, CHEB_SMEM>>>(p_z1, p_z2, p_z3, p_chT + l*8192, chb + l*64);
        k_tconv<<<576, 256, TCONV_SMEM>>>(p_z3, p_z1, p_wT + (l*2 + 1)*36864, tcb + (l*2 + 1)*192);
        k_bnstats<<<768, 256>>>(p_z1);
        k_bnln<<<4608, 256>>>(p_z1, bng + l*N_, bnb + l*N_, lng + l*64, lnb + l*64);
    }

    k_emb<<<768, 256>>>(o1w, o1b);
    dim3 hg(24, 96, 4);
    k_head<<<hg, 256>>>(out, olg, olb, o2w, o2b);
}

// round 4
// speedup vs baseline: 1.5466x; 1.1230x over previous
#include <cuda_runtime.h>
#include <math.h>

#define B_ 4
#define T_ 12
#define N_ 768
#define F_ 32
#define H_ 64
#define E_ 24576
#define M_ (B_*T_*N_)
#define EPS_ 1e-5f

#define CVT_TF32(u, f) asm("cvt.rna.tf32.f32 %0, %1;" : "=r"(u) : "f"(f))

#define MMA_TF32(d0,d1,d2,d3,a0,a1,a2,a3,b0,b1) \
    asm volatile("mma.sync.aligned.m16n8k8.row.col.f32.tf32.tf32.f32 " \
        "{%0,%1,%2,%3}, {%4,%5,%6,%7}, {%8,%9}, {%0,%1,%2,%3};" \
        : "+f"(d0),"+f"(d1),"+f"(d2),"+f"(d3) \
        : "r"(a0),"r"(a1),"r"(a2),"r"(a3),"r"(b0),"r"(b1))

// A tile stride (words): 68 -> conflict-free A-fragment loads
// W tile stride (words): 72 -> conflict-free B-fragment loads
#define SA_STR 68
#define SW_STR 72

// ---------------- device scratch ----------------
__device__ float    g_h [M_*H_];
__device__ float    g_z1[M_*H_];
__device__ float    g_z2[M_*H_];
__device__ float    g_z3[M_*H_];
__device__ unsigned g_wT[4*3*3*H_*H_];   // tf32 bits, [ls][kt][g][hi][ho]
__device__ unsigned g_chT[2*2*H_*H_];    // tf32 bits, [l][k*64+hi][ho]
__device__ float    g_deg[N_];
__device__ int      g_cnt[N_];
__device__ int      g_rowptr[N_+1];
__device__ int      g_cursor[N_];
__device__ float    g_dinv[N_];
__device__ int      g_ccol[E_];
__device__ float    g_cw[E_];
__device__ float    g_mu[N_];
__device__ float    g_rstdv[N_];
__device__ float    g_av[B_*N_*32];
__device__ float    g_cv[B_*N_*32];

// ---------------- graph preprocessing ----------------
__global__ void k_prep0() {
    int i = blockIdx.x*256 + threadIdx.x;
    if (i < N_) { g_deg[i] = 0.f; g_cnt[i] = 0; }
}

__global__ void k_prep1(const int* __restrict__ ei, const float* __restrict__ ew) {
    int e = blockIdx.x*256 + threadIdx.x;
    if (e < E_) {
        int r = ei[e];
        atomicAdd(&g_deg[r], ew[e]);
        atomicAdd(&g_cnt[r], 1);
    }
}

__global__ void k_scan() {
    __shared__ int s[1024];
    int tid = threadIdx.x;
    s[tid] = (tid < N_) ? g_cnt[tid] : 0;
    if (tid < N_) {
        float d = g_deg[tid];
        g_dinv[tid] = (d > 0.f) ? rsqrtf(fmaxf(d, 1e-12f)) : 0.f;
    }
    __syncthreads();
    for (int off = 1; off < 1024; off <<= 1) {
        int v = (tid >= off) ? s[tid-off] : 0;
        __syncthreads();
        s[tid] += v;
        __syncthreads();
    }
    if (tid < N_) {
        int ex = (tid == 0) ? 0 : s[tid-1];
        g_rowptr[tid] = ex;
        g_cursor[tid] = ex;
    }
    if (tid == N_-1) g_rowptr[N_] = s[N_-1];
}

__global__ void k_scatter(const int* __restrict__ ei, const float* __restrict__ ew) {
    int e = blockIdx.x*256 + threadIdx.x;
    if (e < E_) {
        int r = ei[e], c = ei[E_+e];
        int pos = atomicAdd(&g_cursor[r], 1);
        g_ccol[pos] = c;
        g_cw[pos] = -g_dinv[r] * ew[e] * g_dinv[c];
    }
}

// tc_w (L,2,3,ho,hi,kt) -> tf32 g_wT [ls][kt][g][hi][ho]
__global__ void k_wt(const float* __restrict__ w) {
    int idx = blockIdx.x*256 + threadIdx.x;   // 0..147455
    int ho = idx & 63;
    int hi = (idx >> 6) & 63;
    int g  = (idx >> 12) % 3;
    int kt = (idx / 12288) % 3;
    int ls = idx / 36864;
    float v = w[(((ls*3 + g)*64 + ho)*64 + hi)*3 + kt];
    unsigned u; CVT_TF32(u, v);
    g_wT[idx] = u;
}

// cheb_w (L,K,hi,ho) -> tf32 (same layout)
__global__ void k_cwt(const float* __restrict__ w) {
    int idx = blockIdx.x*256 + threadIdx.x;   // 0..16383
    float v = w[idx];
    unsigned u; CVT_TF32(u, v);
    g_chT[idx] = u;
}

// ---------------- input projection ----------------
__global__ void __launch_bounds__(256) k_inproj(const float* __restrict__ x,
    const float* __restrict__ pw, const float* __restrict__ pb) {
    __shared__ float xs[4][32];
    int rl = threadIdx.x >> 6, j = threadIdx.x & 63;
    int row = blockIdx.x*4 + rl;
    if (j < 32) xs[rl][j] = x[(long)row*F_ + j];
    __syncthreads();
    float acc = pb[j];
#pragma unroll
    for (int f = 0; f < 32; f++) acc += xs[rl][f] * pw[f*64 + j];
    g_h[(long)row*H_ + j] = acc;
}

// ---------------- gated temporal conv: tf32 mma.sync ----------------
// block: 64 rows x (3 gates x 64) outs, K=192 (3 kt x 64)
// smem: sA[64][SA_STR] tf32, sW[192][SW_STR] tf32; epilogue overlay sE[64][196] f32
__global__ void __launch_bounds__(256, 2) k_tconv(
    const float* __restrict__ in, float* __restrict__ out,
    const unsigned* __restrict__ wT, const float* __restrict__ bias) {
    extern __shared__ __align__(16) unsigned smem[];
    unsigned* sA = smem;                    // 64*SA_STR
    unsigned* sW = smem + 64*SA_STR;        // 192*SW_STR
    float*    sE = (float*)smem;            // 64*196 (epilogue)

    const int tid  = threadIdx.x;
    const int lane = tid & 31;
    const int w    = tid >> 5;
    const int wm   = w >> 2;          // 0..1
    const int wn   = w & 3;           // 0..3
    const int r0   = blockIdx.x * 64;
    const int t    = (r0 / N_) % T_;
    const int lrow = tid >> 4;        // 0..15
    const int lhi  = (tid & 15) * 4;

    const int aBase = (wm*32 + (lane>>2))*SA_STR + (lane&3);
    int bOff[6];
#pragma unroll
    for (int j = 0; j < 6; j++) {
        int colj = wn*48 + j*8;
        int g = colj >> 6, nin = colj & 63;
        bOff[j] = ((g<<6) + (lane&3))*SW_STR + nin + (lane>>2);
    }

    float d[2][6][4];
#pragma unroll
    for (int mi = 0; mi < 2; mi++)
#pragma unroll
        for (int j = 0; j < 6; j++)
#pragma unroll
            for (int q = 0; q < 4; q++) d[mi][j][q] = 0.f;

    for (int kt = 0; kt < 3; kt++) {
        __syncthreads();
        // fill weights: 3*64*64 tf32 words
        const uint4* wsrc = (const uint4*)(wT + kt*3*4096);
#pragma unroll
        for (int q = 0; q < 12; q++) {
            int idx = q*256 + tid;          // 0..3071 uint4 units
            int ho4 = (idx & 15) * 4;
            int ghi = idx >> 4;             // 0..191
            *(uint4*)(sW + ghi*SW_STR + ho4) = wsrc[idx];
        }
        // fill A with cvt
        const int dt = kt - 1;
        const bool valid = ((unsigned)(t + dt)) < (unsigned)T_;
        const float* src = in + (long)(r0 + dt*N_) * H_;
#pragma unroll
        for (int rr = 0; rr < 4; rr++) {
            int row = lrow + rr*16;
            float4 v = make_float4(0.f,0.f,0.f,0.f);
            if (valid) v = *(const float4*)(src + row*H_ + lhi);
            uint4 u;
            CVT_TF32(u.x, v.x); CVT_TF32(u.y, v.y);
            CVT_TF32(u.z, v.z); CVT_TF32(u.w, v.w);
            *(uint4*)(sA + row*SA_STR + lhi) = u;
        }
        __syncthreads();
#pragma unroll
        for (int ks = 0; ks < 8; ks++) {
            const int ka = aBase + ks*8;
            const int kb = ks*8*SW_STR;
            unsigned a[2][4];
#pragma unroll
            for (int mi = 0; mi < 2; mi++) {
                int base = ka + mi*16*SA_STR;
                a[mi][0] = sA[base];
                a[mi][1] = sA[base + 8*SA_STR];
                a[mi][2] = sA[base + 4];
                a[mi][3] = sA[base + 8*SA_STR + 4];
            }
#pragma unroll
            for (int j = 0; j < 6; j++) {
                unsigned b0 = sW[bOff[j] + kb];
                unsigned b1 = sW[bOff[j] + kb + 4*SW_STR];
#pragma unroll
                for (int mi = 0; mi < 2; mi++)
                    MMA_TF32(d[mi][j][0], d[mi][j][1], d[mi][j][2], d[mi][j][3],
                             a[mi][0], a[mi][1], a[mi][2], a[mi][3], b0, b1);
            }
        }
    }
    // park accumulators in smem for cross-warp gate combine
    __syncthreads();
#pragma unroll
    for (int mi = 0; mi < 2; mi++)
#pragma unroll
        for (int j = 0; j < 6; j++) {
            int r = wm*32 + mi*16 + (lane>>2);
            int c = wn*48 + j*8 + 2*(lane&3);
            *(float2*)&sE[r*196 + c]     = make_float2(d[mi][j][0], d[mi][j][1]);
            *(float2*)&sE[(r+8)*196 + c] = make_float2(d[mi][j][2], d[mi][j][3]);
        }
    __syncthreads();
    // combine: relu(g0*sigmoid(g1)+g2)
    const int col4 = (tid & 15) * 4;
    const int row4 = (tid >> 4) * 4;
#pragma unroll
    for (int i = 0; i < 4; i++) {
        int row = row4 + i;
        float r[4];
#pragma unroll
        for (int jj = 0; jj < 4; jj++) {
            int ho = col4 + jj;
            float y0 = sE[row*196 + ho]        + bias[ho];
            float y1 = sE[row*196 + 64 + ho]   + bias[64 + ho];
            float y2 = sE[row*196 + 128 + ho]  + bias[128 + ho];
            float s = 1.f / (1.f + __expf(-y1));
            r[jj] = fmaxf(y0*s + y2, 0.f);
        }
        *(float4*)(out + (long)(r0 + row)*H_ + col4) = make_float4(r[0],r[1],r[2],r[3]);
    }
}

// ---------------- Laplacian propagation (CSR gather) ----------------
__global__ void __launch_bounds__(256) k_lhat(const float* __restrict__ z, float* __restrict__ out) {
    const int n   = blockIdx.x;
    const int tid = threadIdx.x;
    const int h   = tid & 63;
    const int btg = tid >> 6;
    __shared__ int   s_col[256];
    __shared__ float s_w[256];
    const int e0 = g_rowptr[n], e1 = g_rowptr[n+1];
    float acc[12];
#pragma unroll
    for (int q = 0; q < 12; q++) acc[q] = 0.f;
    for (int base = e0; base < e1; base += 256) {
        int cnt = min(256, e1 - base);
        __syncthreads();
        if (tid < cnt) { s_col[tid] = g_ccol[base + tid]; s_w[tid] = g_cw[base + tid]; }
        __syncthreads();
        for (int e = 0; e < cnt; e++) {
            const float* zp = z + ((long)(btg*12)*N_ + s_col[e])*H_ + h;
            float w = s_w[e];
#pragma unroll
            for (int q = 0; q < 12; q++) acc[q] += w * zp[(long)q * N_ * H_];
        }
    }
#pragma unroll
    for (int q = 0; q < 12; q++)
        out[((long)(btg*12 + q)*N_ + n)*H_ + h] = acc[q];
}

// ---------------- cheb combine via tf32 mma: relu([z0|z1]@[th0;th1] + b) ----------------
// smem: sA[64][132] tf32, sW[128][SW_STR] tf32
#define CA_STR 132
__global__ void __launch_bounds__(256, 2) k_cheb(
    const float* __restrict__ z0, const float* __restrict__ z1,
    float* __restrict__ out,
    const unsigned* __restrict__ th, const float* __restrict__ cb) {
    extern __shared__ __align__(16) unsigned smem[];
    unsigned* sA = smem;                    // 64*CA_STR
    unsigned* sW = smem + 64*CA_STR;        // 128*SW_STR

    const int tid  = threadIdx.x;
    const int lane = tid & 31;
    const int w    = tid >> 5;
    const int wm   = w >> 2;          // 0..1
    const int wn   = w & 3;           // 0..3
    const int r0   = blockIdx.x * 64;
    const int lrow = tid >> 4;
    const int lhi  = (tid & 15) * 4;

    // fill A = [z0 | z1] (cvt to tf32)
#pragma unroll
    for (int rr = 0; rr < 4; rr++) {
        int row = lrow + rr*16;
        float4 v0 = *(const float4*)(z0 + (long)(r0 + row)*H_ + lhi);
        float4 v1 = *(const float4*)(z1 + (long)(r0 + row)*H_ + lhi);
        uint4 u0, u1;
        CVT_TF32(u0.x, v0.x); CVT_TF32(u0.y, v0.y); CVT_TF32(u0.z, v0.z); CVT_TF32(u0.w, v0.w);
        CVT_TF32(u1.x, v1.x); CVT_TF32(u1.y, v1.y); CVT_TF32(u1.z, v1.z); CVT_TF32(u1.w, v1.w);
        *(uint4*)(sA + row*CA_STR + lhi)      = u0;
        *(uint4*)(sA + row*CA_STR + 64 + lhi) = u1;
    }
    // fill W: 128x64 tf32 words
    const uint4* wsrc = (const uint4*)th;
#pragma unroll
    for (int q = 0; q < 8; q++) {
        int idx = q*256 + tid;         // 0..2047 uint4 units
        int ho4 = (idx & 15) * 4;
        int kr  = idx >> 4;            // 0..127
        *(uint4*)(sW + kr*SW_STR + ho4) = wsrc[idx];
    }
    __syncthreads();

    const int aBase = (wm*32 + (lane>>2))*CA_STR + (lane&3);
    int bOff[2];
#pragma unroll
    for (int j = 0; j < 2; j++)
        bOff[j] = (lane&3)*SW_STR + wn*16 + j*8 + (lane>>2);

    float d[2][2][4];
#pragma unroll
    for (int mi = 0; mi < 2; mi++)
#pragma unroll
        for (int j = 0; j < 2; j++)
#pragma unroll
            for (int q = 0; q < 4; q++) d[mi][j][q] = 0.f;

#pragma unroll
    for (int ks = 0; ks < 16; ks++) {
        const int ka = aBase + ks*8;
        const int kb = ks*8*SW_STR;
        unsigned a[2][4];
#pragma unroll
        for (int mi = 0; mi < 2; mi++) {
            int base = ka + mi*16*CA_STR;
            a[mi][0] = sA[base];
            a[mi][1] = sA[base + 8*CA_STR];
            a[mi][2] = sA[base + 4];
            a[mi][3] = sA[base + 8*CA_STR + 4];
        }
#pragma unroll
        for (int j = 0; j < 2; j++) {
            unsigned b0 = sW[bOff[j] + kb];
            unsigned b1 = sW[bOff[j] + kb + 4*SW_STR];
#pragma unroll
            for (int mi = 0; mi < 2; mi++)
                MMA_TF32(d[mi][j][0], d[mi][j][1], d[mi][j][2], d[mi][j][3],
                         a[mi][0], a[mi][1], a[mi][2], a[mi][3], b0, b1);
        }
    }
    // direct epilogue
#pragma unroll
    for (int mi = 0; mi < 2; mi++)
#pragma unroll
        for (int j = 0; j < 2; j++) {
            int r = wm*32 + mi*16 + (lane>>2);
            int c = wn*16 + j*8 + 2*(lane&3);
            float b0 = cb[c], b1 = cb[c+1];
            *(float2*)(out + (long)(r0 + r)*H_ + c) =
                make_float2(fmaxf(d[mi][j][0] + b0, 0.f), fmaxf(d[mi][j][1] + b1, 0.f));
            *(float2*)(out + (long)(r0 + r + 8)*H_ + c) =
                make_float2(fmaxf(d[mi][j][2] + b0, 0.f), fmaxf(d[mi][j][3] + b1, 0.f));
        }
}

// ---------------- BatchNorm stats per node ----------------
__global__ void __launch_bounds__(256) k_bnstats(const float* __restrict__ z) {
    const int n = blockIdx.x;
    const int tid = threadIdx.x;
    double s = 0.0, ss = 0.0;
    for (int idx = tid; idx < B_*T_*H_; idx += 256) {
        int bt = idx >> 6, h = idx & 63;
        float v = z[((long)bt*N_ + n)*H_ + h];
        s += v; ss += (double)v * v;
    }
    __shared__ double sh_s[8], sh_ss[8];
#pragma unroll
    for (int off = 16; off; off >>= 1) {
        s  += __shfl_xor_sync(0xffffffffu, s, off);
        ss += __shfl_xor_sync(0xffffffffu, ss, off);
    }
    int wq = tid >> 5, l = tid & 31;
    if (l == 0) { sh_s[wq] = s; sh_ss[wq] = ss; }
    __syncthreads();
    if (tid == 0) {
        double ts = 0.0, tss = 0.0;
        for (int q = 0; q < 8; q++) { ts += sh_s[q]; tss += sh_ss[q]; }
        double mu  = ts / (double)(B_*T_*H_);
        double var = tss / (double)(B_*T_*H_) - mu*mu;
        g_mu[n]    = (float)mu;
        g_rstdv[n] = rsqrtf((float)var + EPS_);
    }
}

// ---------------- BN apply + LayerNorm + residual ----------------
__global__ void __launch_bounds__(256) k_bnln(
    const float* __restrict__ z,
    const float* __restrict__ bng, const float* __restrict__ bnb,
    const float* __restrict__ lng, const float* __restrict__ lnb) {
    int warp = threadIdx.x >> 5, lane = threadIdx.x & 31;
    int row = blockIdx.x*8 + warp;
    int n = row % N_;
    float mu = g_mu[n], rs = g_rstdv[n];
    float bg = bng[n] * rs, bb = bnb[n];
    float v0 = z[(long)row*H_ + lane];
    float v1 = z[(long)row*H_ + lane + 32];
    float u0 = (v0 - mu)*bg + bb;
    float u1 = (v1 - mu)*bg + bb;
    float sm = u0 + u1;
#pragma unroll
    for (int off = 16; off; off >>= 1) sm += __shfl_xor_sync(0xffffffffu, sm, off);
    float m = sm * (1.f/64.f);
    float d0 = u0 - m, d1 = u1 - m;
    float q = d0*d0 + d1*d1;
#pragma unroll
    for (int off = 16; off; off >>= 1) q += __shfl_xor_sync(0xffffffffu, q, off);
    float r = rsqrtf(q*(1.f/64.f) + EPS_);
    float* hp = g_h + (long)row*H_;
    hp[lane]      += d0*r*lng[lane]      + lnb[lane];
    hp[lane + 32] += d1*r*lng[lane + 32] + lnb[lane + 32];
}

// ---------------- head: a = emb@W1[:64], c = emb@W1[64:] + b1 ----------------
__global__ void __launch_bounds__(256) k_emb(const float* __restrict__ w1, const float* __restrict__ b1) {
    __shared__ float es[4][64];
    int rl = threadIdx.x >> 6, j = threadIdx.x & 63;
    int row = blockIdx.x*4 + rl;
    int b = row / N_, n = row % N_;
    es[rl][j] = g_h[(((long)b*T_ + (T_-1))*N_ + n)*H_ + j];
    __syncthreads();
    if (j < 32) {
        float acc = 0.f;
#pragma unroll
        for (int k = 0; k < 64; k++) acc += es[rl][k] * w1[k*32 + j];
        g_av[row*32 + j] = acc;
    } else {
        int jj = j - 32;
        float acc = b1[jj];
#pragma unroll
        for (int k = 0; k < 64; k++) acc += es[rl][k] * w1[(64 + k)*32 + jj];
        g_cv[row*32 + jj] = acc;
    }
}

// ---------------- pairwise head ----------------
__global__ void __launch_bounds__(256) k_head(
    float* __restrict__ out,
    const float* __restrict__ og, const float* __restrict__ ob,
    const float* __restrict__ w2, const float* __restrict__ b2) {
    __shared__ float sa[8][33], sc[32][33], sgw[32], sob[32];
    int tid = threadIdx.x;
    int b = blockIdx.z, i0 = blockIdx.y*8, j0 = blockIdx.x*32;
    {
        int il = tid >> 5, k = tid & 31;
        sa[il][k] = g_av[((long)b*N_ + i0 + il)*32 + k];
    }
#pragma unroll
    for (int q = 0; q < 4; q++) {
        int idx = q*256 + tid;
        int jl = idx >> 5, k = idx & 31;
        sc[jl][k] = g_cv[((long)b*N_ + j0 + jl)*32 + k];
    }
    if (tid < 32) { sgw[tid] = og[tid]*w2[tid]; sob[tid] = ob[tid]*w2[tid]; }
    __syncthreads();
    int jl = tid & 31, il = tid >> 5;
    float p[32]; float sum = 0.f;
#pragma unroll
    for (int k = 0; k < 32; k++) { p[k] = fmaxf(sa[il][k] + sc[jl][k], 0.f); sum += p[k]; }
    float m = sum * (1.f/32.f);
    float ss = 0.f, dot = 0.f, kc = 0.f;
#pragma unroll
    for (int k = 0; k < 32; k++) {
        float d = p[k] - m;
        ss  += d*d;
        dot += d*sgw[k];
        kc  += sob[k];
    }
    float logit = dot * rsqrtf(ss*(1.f/32.f) + EPS_) + kc + b2[0];
    out[((long)b*N_ + (i0 + il))*N_ + j0 + jl] = 1.f / (1.f + __expf(-logit));
}

// ---------------- orchestration ----------------
extern "C" void kernel_launch(void* const* d_in, const int* in_sizes, int n_in,
                              void* d_out, int out_size) {
    const float* x   = (const float*)d_in[0];
    const int*   ei  = (const int*)  d_in[1];
    const float* ew  = (const float*)d_in[2];
    const float* ipw = (const float*)d_in[3];
    const float* ipb = (const float*)d_in[4];
    const float* tcw = (const float*)d_in[5];
    const float* tcb = (const float*)d_in[6];
    const float* chw = (const float*)d_in[7];
    const float* chb = (const float*)d_in[8];
    const float* bng = (const float*)d_in[9];
    const float* bnb = (const float*)d_in[10];
    const float* lng = (const float*)d_in[11];
    const float* lnb = (const float*)d_in[12];
    const float* o1w = (const float*)d_in[13];
    const float* o1b = (const float*)d_in[14];
    const float* olg = (const float*)d_in[15];
    const float* olb = (const float*)d_in[16];
    const float* o2w = (const float*)d_in[17];
    const float* o2b = (const float*)d_in[18];
    float* out = (float*)d_out;

    const int TCONV_SMEM = (64*SA_STR + 192*SW_STR) * 4;   // 72704
    const int CHEB_SMEM  = (64*CA_STR + 128*SW_STR) * 4;   // 70656
    cudaFuncSetAttribute(k_tconv, cudaFuncAttributeMaxDynamicSharedMemorySize, TCONV_SMEM);
    cudaFuncSetAttribute(k_cheb,  cudaFuncAttributeMaxDynamicSharedMemorySize, CHEB_SMEM);

    float *p_h, *p_z1, *p_z2, *p_z3;
    unsigned *p_wT, *p_chT;
    cudaGetSymbolAddress((void**)&p_h,   g_h);
    cudaGetSymbolAddress((void**)&p_z1,  g_z1);
    cudaGetSymbolAddress((void**)&p_z2,  g_z2);
    cudaGetSymbolAddress((void**)&p_z3,  g_z3);
    cudaGetSymbolAddress((void**)&p_wT,  g_wT);
    cudaGetSymbolAddress((void**)&p_chT, g_chT);

    // order chosen so the profiled launch slot is a k_tconv
    k_wt<<<576, 256>>>(tcw);                 // 0
    k_cwt<<<64, 256>>>(chw);                 // 1
    k_inproj<<<9216, 256>>>(x, ipw, ipb);    // 2
    k_tconv<<<576, 256, TCONV_SMEM>>>(p_h, p_z1, p_wT + 0*36864, tcb + 0*192);  // 3 (layer0 first)
    k_prep0<<<3, 256>>>();                   // 4
    k_prep1<<<96, 256>>>(ei, ew);            // 5
    k_scan<<<1, 1024>>>();                   // 6
    k_scatter<<<96, 256>>>(ei, ew);          // 7

    for (int l = 0; l < 2; l++) {
        if (l > 0)
            k_tconv<<<576, 256, TCONV_SMEM>>>(p_h, p_z1, p_wT + (l*2 + 0)*36864, tcb + (l*2 + 0)*192);
        k_lhat<<<768, 256>>>(p_z1, p_z2);
        k_cheb<<<576, 256, CHEB_SMEM>>>(p_z1, p_z2, p_z3, p_chT + l*8192, chb + l*64);
        k_tconv<<<576, 256, TCONV_SMEM>>>(p_z3, p_z1, p_wT + (l*2 + 1)*36864, tcb + (l*2 + 1)*192);
        k_bnstats<<<768, 256>>>(p_z1);
        k_bnln<<<4608, 256>>>(p_z1, bng + l*N_, bnb + l*N_, lng + l*64, lnb + l*64);
    }

    k_emb<<<768, 256>>>(o1w, o1b);
    dim3 hg(24, 96, 4);
    k_head<<<hg, 256>>>(out, olg, olb, o2w, o2b);
}